// round 3
// baseline (speedup 1.0000x reference)
#include <cuda_runtime.h>
#include <math.h>

#define BB 32
#define CC 273
#define TT 4096
#define OO 270
#define DD 242
#define NF 11
#define C_PAD 288   // padded C stride for embT (mult of 32)
#define O_PAD 272   // padded O stride for hT / weights (mult of 4)

// Scratch (device globals: allocation-free). Padded by 1024 floats so that
// tile-edge float4 overreads (m0+m up to tileCeil-1 past M) stay in-bounds.
__device__ __align__(16) float g_embT[(size_t)BB * DD * C_PAD + 1024]; // [b][d][c]
__device__ __align__(16) float g_hT  [(size_t)BB * DD * O_PAD + 1024]; // [b][d][o]
__device__ __align__(16) float g_w   [(size_t)BB * CC * O_PAD + 1024]; // [b][c][o] scores->weights
__device__ float g_off[(size_t)BB * CC];

// ---------------------------------------------------------------------------
// Kernel 1: Fourier embedding, written transposed [b][d][c], + invalid offset
// grid (ceil(C/32), B), block (32, 8)
// ---------------------------------------------------------------------------
__global__ void embed_kernel(const float* __restrict__ pos) {
    int b = blockIdx.y;
    int c = blockIdx.x * 32 + threadIdx.x;
    if (c >= CC) return;
    float x = pos[((size_t)b * CC + c) * 2 + 0];
    float y = pos[((size_t)b * CC + c) * 2 + 1];
    if (threadIdx.y == 0) {
        g_off[(size_t)b * CC + c] = (x == -0.1f && y == -0.1f) ? -1e9f : 0.0f;
    }
    const float scale = (float)(2.0 * 3.14159265358979323846 / 1.4);
    float px = x + 0.2f, py = y + 0.2f;
    float* eb = g_embT + (size_t)b * (DD * C_PAD);
    for (int k = threadIdx.y; k < NF * NF; k += blockDim.y) {
        int i = k / NF, j = k % NF;
        float loc = px * (scale * (float)i) + py * (scale * (float)j);
        float s, co;
        sincosf(loc, &s, &co);
        eb[(size_t)k * C_PAD + c] = co;              // cos block: d = k
        eb[(size_t)(NF * NF + k) * C_PAD + c] = s;   // sin block: d = 121 + k
    }
}

// ---------------------------------------------------------------------------
// Kernel 2: per-batch heads gather + transpose -> hT[b][d][o]
// grid (ceil(D/32), ceil(O/32), B), block (32, 8)
// ---------------------------------------------------------------------------
__global__ void gather_heads_kernel(const float* __restrict__ heads,
                                    const int* __restrict__ subj) {
    __shared__ float tile[32][33];
    int b = blockIdx.z;
    int s = subj[b];
    int d0 = blockIdx.x * 32;
    int o0 = blockIdx.y * 32;
    const float* hb = heads + (size_t)s * OO * DD;
    for (int oy = threadIdx.y; oy < 32; oy += blockDim.y) {
        int o = o0 + oy;
        int d = d0 + threadIdx.x;
        tile[oy][threadIdx.x] = (o < OO && d < DD) ? hb[(size_t)o * DD + d] : 0.0f;
    }
    __syncthreads();
    float* ht = g_hT + (size_t)b * (DD * O_PAD);
    for (int dy = threadIdx.y; dy < 32; dy += blockDim.y) {
        int d = d0 + dy;
        int o = o0 + threadIdx.x;
        if (d < DD && o < OO) ht[(size_t)d * O_PAD + o] = tile[threadIdx.x][dy];
    }
}

// ---------------------------------------------------------------------------
// Generic batched "C = A^T B" GEMM. A: [b][K][lda] (M along lda rows),
// B: [b][K][ldb] (N along rows), C: [b][M][ldc]. Optional per-m offset add.
// ---------------------------------------------------------------------------
template<int BM, int BN, int BK, int TM, int TN, bool OFF>
__global__ void gemm_tn(const float* __restrict__ A, const float* __restrict__ B,
                        float* __restrict__ C, const float* __restrict__ off,
                        int M, int N, int K,
                        int lda, int ldb, int ldc,
                        size_t sA, size_t sB, size_t sC) {
    constexpr int THREADS = (BM / TM) * (BN / TN);
    constexpr int NX = BN / TN;
    __shared__ float As[BK][BM];
    __shared__ float Bs[BK][BN];

    int b = blockIdx.z;
    const float* Ab = A + (size_t)b * sA;
    const float* Bb = B + (size_t)b * sB;
    float* Cb = C + (size_t)b * sC;

    int m0 = blockIdx.y * BM;
    int n0 = blockIdx.x * BN;
    int tid = threadIdx.x;
    int tx = tid % NX;
    int ty = tid / NX;

    float acc[TM][TN];
#pragma unroll
    for (int i = 0; i < TM; i++)
#pragma unroll
        for (int j = 0; j < TN; j++) acc[i][j] = 0.0f;

    for (int k0 = 0; k0 < K; k0 += BK) {
        for (int i = tid * 4; i < BK * BM; i += THREADS * 4) {
            int k = i / BM, m = i % BM;
            float4 v = make_float4(0.f, 0.f, 0.f, 0.f);
            if (k0 + k < K)
                v = *(const float4*)(Ab + (size_t)(k0 + k) * lda + m0 + m);
            *(float4*)(&As[k][m]) = v;
        }
        for (int i = tid * 4; i < BK * BN; i += THREADS * 4) {
            int k = i / BN, n = i % BN;
            float4 v = make_float4(0.f, 0.f, 0.f, 0.f);
            if (k0 + k < K)
                v = *(const float4*)(Bb + (size_t)(k0 + k) * ldb + n0 + n);
            *(float4*)(&Bs[k][n]) = v;
        }
        __syncthreads();
#pragma unroll
        for (int k = 0; k < BK; k++) {
            float a[TM], bb[TN];
#pragma unroll
            for (int i = 0; i < TM; i++) a[i] = As[k][ty * TM + i];
#pragma unroll
            for (int j = 0; j < TN; j++) bb[j] = Bs[k][tx * TN + j];
#pragma unroll
            for (int i = 0; i < TM; i++)
#pragma unroll
                for (int j = 0; j < TN; j++)
                    acc[i][j] = fmaf(a[i], bb[j], acc[i][j]);
        }
        __syncthreads();
    }

#pragma unroll
    for (int i = 0; i < TM; i++) {
        int m = m0 + ty * TM + i;
        if (m >= M) continue;
        float ofs = OFF ? off[(size_t)b * M + m] : 0.0f;
#pragma unroll
        for (int j = 0; j < TN; j++) {
            int n = n0 + tx * TN + j;
            if (n < N) Cb[(size_t)m * ldc + n] = acc[i][j] + ofs;
        }
    }
}

// ---------------------------------------------------------------------------
// Kernel 4: softmax over channels c (columns of g_w[b][:,o]), in place.
// grid (ceil(O/32), B), block 32
// ---------------------------------------------------------------------------
__global__ void softmax_kernel() {
    int b = blockIdx.y;
    int o = blockIdx.x * 32 + threadIdx.x;
    if (o >= OO) return;
    float* col = g_w + (size_t)b * (CC * O_PAD) + o;
    float mx = -3.0e38f;
    for (int c = 0; c < CC; c++) mx = fmaxf(mx, col[(size_t)c * O_PAD]);
    float s = 0.0f;
    for (int c = 0; c < CC; c++) {
        float e = expf(col[(size_t)c * O_PAD] - mx);
        col[(size_t)c * O_PAD] = e;
        s += e;
    }
    float inv = 1.0f / s;
    for (int c = 0; c < CC; c++) col[(size_t)c * O_PAD] *= inv;
}

// ---------------------------------------------------------------------------

extern "C" void kernel_launch(void* const* d_in, const int* in_sizes, int n_in,
                              void* d_out, int out_size) {
    const float* meg   = (const float*)d_in[0];   // [B,C,T]
    const float* pos   = (const float*)d_in[1];   // [B,C,2]
    const int*   subj  = (const int*)d_in[2];     // [B]
    const float* heads = (const float*)d_in[3];   // [200,O,D]
    float* out = (float*)d_out;                   // [B,O,T]

    float *p_embT, *p_hT, *p_w, *p_off;
    cudaGetSymbolAddress((void**)&p_embT, g_embT);
    cudaGetSymbolAddress((void**)&p_hT,   g_hT);
    cudaGetSymbolAddress((void**)&p_w,    g_w);
    cudaGetSymbolAddress((void**)&p_off,  g_off);

    // 1) Fourier embedding (transposed) + invalid offsets
    embed_kernel<<<dim3((CC + 31) / 32, BB), dim3(32, 8)>>>(pos);

    // 2) heads gather + transpose
    gather_heads_kernel<<<dim3((DD + 31) / 32, (OO + 31) / 32, BB), dim3(32, 8)>>>(heads, subj);

    // 3) scores[b][c][o] = sum_d embT[d][c] * hT[d][o] + off[c]
    //    M=C=273, N=O=270, K=D=242
    gemm_tn<64, 64, 16, 4, 4, true><<<dim3((OO + 63) / 64, (CC + 63) / 64, BB), 256>>>(
        p_embT, p_hT, p_w, p_off,
        CC, OO, DD,
        C_PAD, O_PAD, O_PAD,
        (size_t)DD * C_PAD, (size_t)DD * O_PAD, (size_t)CC * O_PAD);

    // 4) softmax over c per (b, o), in place on g_w
    softmax_kernel<<<dim3((OO + 31) / 32, BB), 32>>>();

    // 5) out[b][o][t] = sum_c w[b][c][o] * meg[b][c][t]
    //    M=O=270, N=T=4096, K=C=273
    gemm_tn<64, 128, 16, 4, 8, false><<<dim3(TT / 128, (OO + 63) / 64, BB), 256>>>(
        p_w, meg, out, nullptr,
        OO, TT, CC,
        O_PAD, TT, TT,
        (size_t)CC * O_PAD, (size_t)CC * TT, (size_t)OO * TT);
}

// round 5
// speedup vs baseline: 2.5769x; 2.5769x over previous
#include <cuda_runtime.h>
#include <math.h>
#include <stdint.h>

#define BB 32
#define CC 273
#define TT 4096
#define OO 270
#define DD 242
#define NF 11
#define C_PAD 288   // padded C stride for embT
#define O_PAD 272   // padded O stride for hT / weights

// Scratch (device globals: allocation-free). Extra pad covers tile-edge
// float4 overreads (m up to 319 on a 270-row matrix etc.).
__device__ __align__(16) float g_embT[(size_t)BB * DD * C_PAD + 1024]; // [b][d][c]
__device__ __align__(16) float g_hT  [(size_t)BB * DD * O_PAD + 1024]; // [b][d][o]
__device__ __align__(16) float g_w   [(size_t)BB * CC * O_PAD + 16384]; // [b][c][o]
__device__ float g_off[(size_t)BB * CC];

// ---------------------------------------------------------------------------
// Kernel 1: Fourier embedding, transposed [b][d][c], + invalid offset
// ---------------------------------------------------------------------------
__global__ void embed_kernel(const float* __restrict__ pos) {
    int b = blockIdx.y;
    int c = blockIdx.x * 32 + threadIdx.x;
    if (c >= CC) return;
    float x = pos[((size_t)b * CC + c) * 2 + 0];
    float y = pos[((size_t)b * CC + c) * 2 + 1];
    if (threadIdx.y == 0) {
        g_off[(size_t)b * CC + c] = (x == -0.1f && y == -0.1f) ? -1e9f : 0.0f;
    }
    const float scale = (float)(2.0 * 3.14159265358979323846 / 1.4);
    float px = x + 0.2f, py = y + 0.2f;
    float* eb = g_embT + (size_t)b * (DD * C_PAD);
    for (int k = threadIdx.y; k < NF * NF; k += blockDim.y) {
        int i = k / NF, j = k % NF;
        float loc = px * (scale * (float)i) + py * (scale * (float)j);
        float s, co;
        sincosf(loc, &s, &co);
        eb[(size_t)k * C_PAD + c] = co;
        eb[(size_t)(NF * NF + k) * C_PAD + c] = s;
    }
}

// ---------------------------------------------------------------------------
// Kernel 2: heads gather + transpose -> hT[b][d][o]
// ---------------------------------------------------------------------------
__global__ void gather_heads_kernel(const float* __restrict__ heads,
                                    const int* __restrict__ subj) {
    __shared__ float tile[32][33];
    int b = blockIdx.z;
    int s = subj[b];
    int d0 = blockIdx.x * 32;
    int o0 = blockIdx.y * 32;
    const float* hb = heads + (size_t)s * OO * DD;
    for (int oy = threadIdx.y; oy < 32; oy += blockDim.y) {
        int o = o0 + oy;
        int d = d0 + threadIdx.x;
        tile[oy][threadIdx.x] = (o < OO && d < DD) ? hb[(size_t)o * DD + d] : 0.0f;
    }
    __syncthreads();
    float* ht = g_hT + (size_t)b * (DD * O_PAD);
    for (int dy = threadIdx.y; dy < 32; dy += blockDim.y) {
        int d = d0 + dy;
        int o = o0 + threadIdx.x;
        if (d < DD && o < OO) ht[(size_t)d * O_PAD + o] = tile[threadIdx.x][dy];
    }
}

// ---------------------------------------------------------------------------
// fp32 SIMT GEMM (kept for scores: accuracy budget). C = A^T B, K-major.
// ---------------------------------------------------------------------------
template<int BM, int BN, int BK, int TM, int TN, bool OFF>
__global__ void gemm_tn(const float* __restrict__ A, const float* __restrict__ B,
                        float* __restrict__ C, const float* __restrict__ off,
                        int M, int N, int K,
                        int lda, int ldb, int ldc,
                        size_t sA, size_t sB, size_t sC) {
    constexpr int THREADS = (BM / TM) * (BN / TN);
    constexpr int NX = BN / TN;
    __shared__ float As[BK][BM];
    __shared__ float Bs[BK][BN];

    int b = blockIdx.z;
    const float* Ab = A + (size_t)b * sA;
    const float* Bb = B + (size_t)b * sB;
    float* Cb = C + (size_t)b * sC;

    int m0 = blockIdx.y * BM;
    int n0 = blockIdx.x * BN;
    int tid = threadIdx.x;
    int tx = tid % NX;
    int ty = tid / NX;

    float acc[TM][TN];
#pragma unroll
    for (int i = 0; i < TM; i++)
#pragma unroll
        for (int j = 0; j < TN; j++) acc[i][j] = 0.0f;

    for (int k0 = 0; k0 < K; k0 += BK) {
        for (int i = tid * 4; i < BK * BM; i += THREADS * 4) {
            int k = i / BM, m = i % BM;
            float4 v = make_float4(0.f, 0.f, 0.f, 0.f);
            if (k0 + k < K)
                v = *(const float4*)(Ab + (size_t)(k0 + k) * lda + m0 + m);
            *(float4*)(&As[k][m]) = v;
        }
        for (int i = tid * 4; i < BK * BN; i += THREADS * 4) {
            int k = i / BN, n = i % BN;
            float4 v = make_float4(0.f, 0.f, 0.f, 0.f);
            if (k0 + k < K)
                v = *(const float4*)(Bb + (size_t)(k0 + k) * ldb + n0 + n);
            *(float4*)(&Bs[k][n]) = v;
        }
        __syncthreads();
#pragma unroll
        for (int k = 0; k < BK; k++) {
            float a[TM], bb[TN];
#pragma unroll
            for (int i = 0; i < TM; i++) a[i] = As[k][ty * TM + i];
#pragma unroll
            for (int j = 0; j < TN; j++) bb[j] = Bs[k][tx * TN + j];
#pragma unroll
            for (int i = 0; i < TM; i++)
#pragma unroll
                for (int j = 0; j < TN; j++)
                    acc[i][j] = fmaf(a[i], bb[j], acc[i][j]);
        }
        __syncthreads();
    }

#pragma unroll
    for (int i = 0; i < TM; i++) {
        int m = m0 + ty * TM + i;
        if (m >= M) continue;
        float ofs = OFF ? off[(size_t)b * M + m] : 0.0f;
#pragma unroll
        for (int j = 0; j < TN; j++) {
            int n = n0 + tx * TN + j;
            if (n < N) Cb[(size_t)m * ldc + n] = acc[i][j] + ofs;
        }
    }
}

// ---------------------------------------------------------------------------
// Kernel 4: softmax over c per (b,o), in place on g_w columns.
// ---------------------------------------------------------------------------
__global__ void softmax_kernel() {
    int b = blockIdx.y;
    int o = blockIdx.x * 32 + threadIdx.x;
    if (o >= OO) return;
    float* col = g_w + (size_t)b * (CC * O_PAD) + o;
    float mx = -3.0e38f;
    for (int c = 0; c < CC; c++) mx = fmaxf(mx, col[(size_t)c * O_PAD]);
    float s = 0.0f;
    for (int c = 0; c < CC; c++) {
        float e = expf(col[(size_t)c * O_PAD] - mx);
        col[(size_t)c * O_PAD] = e;
        s += e;
    }
    float inv = 1.0f / s;
    for (int c = 0; c < CC; c++) col[(size_t)c * O_PAD] *= inv;
}

// ---------------------------------------------------------------------------
// Kernel 5: TF32 tensor-core GEMM for the dominant contraction.
// out[b][m][n] = sum_k A[b][k][m] * B[b][k][n]
// A = weights g_w (lda=O_PAD), B = meg (ldb=TT). M=270, N=4096, K=273.
// Block: 256 thr (8 warps, 2x4), BM=64, BN=128, BK=16.
// Each warp: 32x32 via 2x4 m16n8k8 tf32 mma tiles.
// ---------------------------------------------------------------------------
__device__ __forceinline__ uint32_t f2tf32(float f) {
    uint32_t r;
    asm("cvt.rna.tf32.f32 %0, %1;" : "=r"(r) : "f"(f));
    return r;
}

#define TBM 64
#define TBN 128
#define TBK 16
#define A_STR (TBM + 4)   // 68: padded to spread banks for fragment LDS
#define B_STR (TBN + 4)   // 132

__global__ __launch_bounds__(256) void gemm_tf32_kernel(
    const float* __restrict__ A, const float* __restrict__ B,
    float* __restrict__ C) {
    __shared__ uint32_t As[TBK][A_STR];
    __shared__ uint32_t Bs[TBK][B_STR];

    int b = blockIdx.z;
    const float* Ab = A + (size_t)b * ((size_t)CC * O_PAD);
    const float* Bb = B + (size_t)b * ((size_t)CC * TT);
    float* Cb = C + (size_t)b * ((size_t)OO * TT);

    int m0 = blockIdx.y * TBM;
    int n0 = blockIdx.x * TBN;
    int tid = threadIdx.x;
    int warpId = tid >> 5;
    int lane = tid & 31;
    int warpM = warpId & 1;        // 2 warps along M (2*32=64)
    int warpN = warpId >> 1;       // 4 warps along N (4*32=128)
    int groupID = lane >> 2;
    int tig = lane & 3;

    float acc[2][4][4];
#pragma unroll
    for (int mt = 0; mt < 2; mt++)
#pragma unroll
        for (int nt = 0; nt < 4; nt++)
#pragma unroll
            for (int r = 0; r < 4; r++) acc[mt][nt][r] = 0.0f;

    for (int k0 = 0; k0 < CC; k0 += TBK) {
        // Fill As: 16x64 = 1024 floats, 256 threads * 4 (float4)
        {
            int i = tid * 4;
            int k = i / TBM, m = i % TBM;
            float4 v = make_float4(0.f, 0.f, 0.f, 0.f);
            if (k0 + k < CC)
                v = *(const float4*)(Ab + (size_t)(k0 + k) * O_PAD + m0 + m);
            As[k][m + 0] = f2tf32(v.x);
            As[k][m + 1] = f2tf32(v.y);
            As[k][m + 2] = f2tf32(v.z);
            As[k][m + 3] = f2tf32(v.w);
        }
        // Fill Bs: 16x128 = 2048 floats, 2 float4 per thread
#pragma unroll
        for (int it = 0; it < 2; it++) {
            int i = (tid + it * 256) * 4;
            int k = i / TBN, n = i % TBN;
            float4 v = make_float4(0.f, 0.f, 0.f, 0.f);
            if (k0 + k < CC)
                v = *(const float4*)(Bb + (size_t)(k0 + k) * TT + n0 + n);
            Bs[k][n + 0] = f2tf32(v.x);
            Bs[k][n + 1] = f2tf32(v.y);
            Bs[k][n + 2] = f2tf32(v.z);
            Bs[k][n + 3] = f2tf32(v.w);
        }
        __syncthreads();

#pragma unroll
        for (int kk = 0; kk < TBK; kk += 8) {
            uint32_t afrag[2][4];
#pragma unroll
            for (int mt = 0; mt < 2; mt++) {
                int mb = warpM * 32 + mt * 16;
                afrag[mt][0] = As[kk + tig][mb + groupID];
                afrag[mt][1] = As[kk + tig][mb + groupID + 8];
                afrag[mt][2] = As[kk + tig + 4][mb + groupID];
                afrag[mt][3] = As[kk + tig + 4][mb + groupID + 8];
            }
            uint32_t bfrag[4][2];
#pragma unroll
            for (int nt = 0; nt < 4; nt++) {
                int nb = warpN * 32 + nt * 8;
                bfrag[nt][0] = Bs[kk + tig][nb + groupID];
                bfrag[nt][1] = Bs[kk + tig + 4][nb + groupID];
            }
#pragma unroll
            for (int mt = 0; mt < 2; mt++)
#pragma unroll
                for (int nt = 0; nt < 4; nt++) {
                    asm volatile(
                        "mma.sync.aligned.m16n8k8.row.col.f32.tf32.tf32.f32 "
                        "{%0,%1,%2,%3}, {%4,%5,%6,%7}, {%8,%9}, {%0,%1,%2,%3};"
                        : "+f"(acc[mt][nt][0]), "+f"(acc[mt][nt][1]),
                          "+f"(acc[mt][nt][2]), "+f"(acc[mt][nt][3])
                        : "r"(afrag[mt][0]), "r"(afrag[mt][1]),
                          "r"(afrag[mt][2]), "r"(afrag[mt][3]),
                          "r"(bfrag[nt][0]), "r"(bfrag[nt][1]));
                }
        }
        __syncthreads();
    }

    // Epilogue: c0,c1 at (row=groupID, col=tig*2, tig*2+1); c2,c3 at row+8
#pragma unroll
    for (int mt = 0; mt < 2; mt++) {
        int mrow0 = m0 + warpM * 32 + mt * 16 + groupID;
#pragma unroll
        for (int nt = 0; nt < 4; nt++) {
            int ncol = n0 + warpN * 32 + nt * 8 + tig * 2;
            if (mrow0 < OO) {
                float2 v = make_float2(acc[mt][nt][0], acc[mt][nt][1]);
                *(float2*)(Cb + (size_t)mrow0 * TT + ncol) = v;
            }
            if (mrow0 + 8 < OO) {
                float2 v = make_float2(acc[mt][nt][2], acc[mt][nt][3]);
                *(float2*)(Cb + (size_t)(mrow0 + 8) * TT + ncol) = v;
            }
        }
    }
}

// ---------------------------------------------------------------------------

extern "C" void kernel_launch(void* const* d_in, const int* in_sizes, int n_in,
                              void* d_out, int out_size) {
    const float* meg   = (const float*)d_in[0];   // [B,C,T]
    const float* pos   = (const float*)d_in[1];   // [B,C,2]
    const int*   subj  = (const int*)d_in[2];     // [B]
    const float* heads = (const float*)d_in[3];   // [200,O,D]
    float* out = (float*)d_out;                   // [B,O,T]

    float *p_embT, *p_hT, *p_w, *p_off;
    cudaGetSymbolAddress((void**)&p_embT, g_embT);
    cudaGetSymbolAddress((void**)&p_hT,   g_hT);
    cudaGetSymbolAddress((void**)&p_w,    g_w);
    cudaGetSymbolAddress((void**)&p_off,  g_off);

    // 1) Fourier embedding (transposed) + invalid offsets
    embed_kernel<<<dim3((CC + 31) / 32, BB), dim3(32, 8)>>>(pos);

    // 2) heads gather + transpose
    gather_heads_kernel<<<dim3((DD + 31) / 32, (OO + 31) / 32, BB), dim3(32, 8)>>>(heads, subj);

    // 3) scores[b][c][o] = sum_d embT[d][c] * hT[d][o] + off[c]  (fp32 exact)
    gemm_tn<64, 64, 16, 4, 4, true><<<dim3((OO + 63) / 64, (CC + 63) / 64, BB), 256>>>(
        p_embT, p_hT, p_w, p_off,
        CC, OO, DD,
        C_PAD, O_PAD, O_PAD,
        (size_t)DD * C_PAD, (size_t)DD * O_PAD, (size_t)CC * O_PAD);

    // 4) softmax over c per (b,o), in place
    softmax_kernel<<<dim3((OO + 31) / 32, BB), 32>>>();

    // 5) out[b][o][t] = sum_c w[b][c][o] * meg[b][c][t]  -- TF32 tensor cores
    gemm_tf32_kernel<<<dim3(TT / TBN, (OO + TBM - 1) / TBM, BB), 256>>>(
        p_w, meg, out);
}

// round 7
// speedup vs baseline: 2.9330x; 1.1382x over previous
#include <cuda_runtime.h>
#include <math.h>
#include <stdint.h>

#define BB 32
#define CC 273
#define TT 4096
#define OO 270
#define DD 242
#define NF 11
#define C_PAD 288   // padded C stride for embT
#define O_PAD 272   // padded O stride for hT / weights

// Scratch (device globals: allocation-free). Extra pad covers tile-edge
// float4 / cp.async overreads.
__device__ __align__(16) float g_embT[(size_t)BB * DD * C_PAD + 1024]; // [b][d][c]
__device__ __align__(16) float g_hT  [(size_t)BB * DD * O_PAD + 1024]; // [b][d][o]
__device__ __align__(16) float g_w   [(size_t)BB * CC * O_PAD + 16384]; // [b][c][o]
__device__ float g_off[(size_t)BB * CC];

// ---------------------------------------------------------------------------
// Kernel 1: Fourier embedding, transposed [b][d][c], + invalid offset
// ---------------------------------------------------------------------------
__global__ void embed_kernel(const float* __restrict__ pos) {
    int b = blockIdx.y;
    int c = blockIdx.x * 32 + threadIdx.x;
    if (c >= CC) return;
    float x = pos[((size_t)b * CC + c) * 2 + 0];
    float y = pos[((size_t)b * CC + c) * 2 + 1];
    if (threadIdx.y == 0) {
        g_off[(size_t)b * CC + c] = (x == -0.1f && y == -0.1f) ? -1e9f : 0.0f;
    }
    const float scale = (float)(2.0 * 3.14159265358979323846 / 1.4);
    float px = x + 0.2f, py = y + 0.2f;
    float* eb = g_embT + (size_t)b * (DD * C_PAD);
    for (int k = threadIdx.y; k < NF * NF; k += blockDim.y) {
        int i = k / NF, j = k % NF;
        float loc = px * (scale * (float)i) + py * (scale * (float)j);
        float s, co;
        sincosf(loc, &s, &co);
        eb[(size_t)k * C_PAD + c] = co;
        eb[(size_t)(NF * NF + k) * C_PAD + c] = s;
    }
}

// ---------------------------------------------------------------------------
// Kernel 2: heads gather + transpose -> hT[b][d][o]
// ---------------------------------------------------------------------------
__global__ void gather_heads_kernel(const float* __restrict__ heads,
                                    const int* __restrict__ subj) {
    __shared__ float tile[32][33];
    int b = blockIdx.z;
    int s = subj[b];
    int d0 = blockIdx.x * 32;
    int o0 = blockIdx.y * 32;
    const float* hb = heads + (size_t)s * OO * DD;
    for (int oy = threadIdx.y; oy < 32; oy += blockDim.y) {
        int o = o0 + oy;
        int d = d0 + threadIdx.x;
        tile[oy][threadIdx.x] = (o < OO && d < DD) ? hb[(size_t)o * DD + d] : 0.0f;
    }
    __syncthreads();
    float* ht = g_hT + (size_t)b * (DD * O_PAD);
    for (int dy = threadIdx.y; dy < 32; dy += blockDim.y) {
        int d = d0 + dy;
        int o = o0 + threadIdx.x;
        if (d < DD && o < OO) ht[(size_t)d * O_PAD + o] = tile[threadIdx.x][dy];
    }
}

// ---------------------------------------------------------------------------
// fp32 SIMT GEMM (scores: keeps softmax inputs fp32-exact). C = A^T B.
// ---------------------------------------------------------------------------
template<int BM, int BN, int BK, int TM, int TN, bool OFF>
__global__ void gemm_tn(const float* __restrict__ A, const float* __restrict__ B,
                        float* __restrict__ C, const float* __restrict__ off,
                        int M, int N, int K,
                        int lda, int ldb, int ldc,
                        size_t sA, size_t sB, size_t sC) {
    constexpr int THREADS = (BM / TM) * (BN / TN);
    constexpr int NX = BN / TN;
    __shared__ float As[BK][BM];
    __shared__ float Bs[BK][BN];

    int b = blockIdx.z;
    const float* Ab = A + (size_t)b * sA;
    const float* Bb = B + (size_t)b * sB;
    float* Cb = C + (size_t)b * sC;

    int m0 = blockIdx.y * BM;
    int n0 = blockIdx.x * BN;
    int tid = threadIdx.x;
    int tx = tid % NX;
    int ty = tid / NX;

    float acc[TM][TN];
#pragma unroll
    for (int i = 0; i < TM; i++)
#pragma unroll
        for (int j = 0; j < TN; j++) acc[i][j] = 0.0f;

    for (int k0 = 0; k0 < K; k0 += BK) {
        for (int i = tid * 4; i < BK * BM; i += THREADS * 4) {
            int k = i / BM, m = i % BM;
            float4 v = make_float4(0.f, 0.f, 0.f, 0.f);
            if (k0 + k < K)
                v = *(const float4*)(Ab + (size_t)(k0 + k) * lda + m0 + m);
            *(float4*)(&As[k][m]) = v;
        }
        for (int i = tid * 4; i < BK * BN; i += THREADS * 4) {
            int k = i / BN, n = i % BN;
            float4 v = make_float4(0.f, 0.f, 0.f, 0.f);
            if (k0 + k < K)
                v = *(const float4*)(Bb + (size_t)(k0 + k) * ldb + n0 + n);
            *(float4*)(&Bs[k][n]) = v;
        }
        __syncthreads();
#pragma unroll
        for (int k = 0; k < BK; k++) {
            float a[TM], bb[TN];
#pragma unroll
            for (int i = 0; i < TM; i++) a[i] = As[k][ty * TM + i];
#pragma unroll
            for (int j = 0; j < TN; j++) bb[j] = Bs[k][tx * TN + j];
#pragma unroll
            for (int i = 0; i < TM; i++)
#pragma unroll
                for (int j = 0; j < TN; j++)
                    acc[i][j] = fmaf(a[i], bb[j], acc[i][j]);
        }
        __syncthreads();
    }

#pragma unroll
    for (int i = 0; i < TM; i++) {
        int m = m0 + ty * TM + i;
        if (m >= M) continue;
        float ofs = OFF ? off[(size_t)b * M + m] : 0.0f;
#pragma unroll
        for (int j = 0; j < TN; j++) {
            int n = n0 + tx * TN + j;
            if (n < N) Cb[(size_t)m * ldc + n] = acc[i][j] + ofs;
        }
    }
}

// ---------------------------------------------------------------------------
// Kernel 4: softmax over c per (b,o), in place. Block (32 o, 8 c-slices).
// grid (ceil(OO/32)=9, BB)
// ---------------------------------------------------------------------------
__global__ void softmax_kernel() {
    __shared__ float red[8][33];
    int b = blockIdx.y;
    int tx = threadIdx.x;          // o within tile
    int ty = threadIdx.y;          // c slice
    int o = blockIdx.x * 32 + tx;
    bool active = (o < OO);
    float* col = g_w + (size_t)b * (CC * O_PAD) + (active ? o : 0);

    float mx = -3.0e38f;
    for (int c = ty; c < CC; c += 8)
        if (active) mx = fmaxf(mx, col[(size_t)c * O_PAD]);
    red[ty][tx] = mx;
    __syncthreads();
    if (ty == 0) {
#pragma unroll
        for (int r = 1; r < 8; r++) mx = fmaxf(mx, red[r][tx]);
        red[0][tx] = mx;
    }
    __syncthreads();
    mx = red[0][tx];
    __syncthreads();

    float s = 0.0f;
    for (int c = ty; c < CC; c += 8) {
        if (active) {
            float e = expf(col[(size_t)c * O_PAD] - mx);
            col[(size_t)c * O_PAD] = e;
            s += e;
        }
    }
    red[ty][tx] = s;
    __syncthreads();
    if (ty == 0) {
#pragma unroll
        for (int r = 1; r < 8; r++) s += red[r][tx];
        red[0][tx] = 1.0f / s;
    }
    __syncthreads();
    float inv = red[0][tx];

    for (int c = ty; c < CC; c += 8)
        if (active) col[(size_t)c * O_PAD] *= inv;
}

// ---------------------------------------------------------------------------
// Kernel 5: TF32 tensor-core GEMM, double-buffered cp.async mainloop.
// out[b][m][n] = sum_k A[b][k][m] * B[b][k][n]
// A = g_w (lda=O_PAD), B = meg (ldb=TT). M=270, N=4096, K=273.
// 256 thr (2x4 warps), BM=64, BN=128, BK=16; warp = 32x32 via 2x4 m16n8k8.
// Raw fp32 bits fed to mma.tf32 (HW rounds); cp.async zero-fills K edge.
// ---------------------------------------------------------------------------
#define TBM 64
#define TBN 128
#define TBK 16
#define A_STR (TBM + 4)   // 68
#define B_STR (TBN + 4)   // 132
#define NTILES ((CC + TBK - 1) / TBK)   // 18

__device__ __forceinline__ void cp16(uint32_t dst, const void* src, bool pred) {
    int sz = pred ? 16 : 0;
    asm volatile("cp.async.cg.shared.global [%0], [%1], 16, %2;"
                 :: "r"(dst), "l"(src), "r"(sz) : "memory");
}

__global__ __launch_bounds__(256) void gemm_tf32_kernel(
    const float* __restrict__ A, const float* __restrict__ B,
    float* __restrict__ C) {
    __shared__ uint32_t As[2][TBK][A_STR];
    __shared__ uint32_t Bs[2][TBK][B_STR];

    int b = blockIdx.z;
    const float* Ab = A + (size_t)b * ((size_t)CC * O_PAD);
    const float* Bb = B + (size_t)b * ((size_t)CC * TT);
    float* Cb = C + (size_t)b * ((size_t)OO * TT);

    int m0 = blockIdx.y * TBM;
    int n0 = blockIdx.x * TBN;
    int tid = threadIdx.x;
    int warpId = tid >> 5;
    int lane = tid & 31;
    int warpM = warpId & 1;
    int warpN = warpId >> 1;
    int groupID = lane >> 2;
    int tig = lane & 3;

    // Per-thread load coordinates (fixed across tiles)
    int ia = tid * 4;
    int ka = ia / TBM, ma = ia % TBM;
    int ib0 = tid * 4;
    int kb0 = ib0 / TBN, nb0 = ib0 % TBN;
    int ib1 = (tid + 256) * 4;
    int kb1 = ib1 / TBN, nb1 = ib1 % TBN;

    float acc[2][4][4];
#pragma unroll
    for (int mt = 0; mt < 2; mt++)
#pragma unroll
        for (int nt = 0; nt < 4; nt++)
#pragma unroll
            for (int r = 0; r < 4; r++) acc[mt][nt][r] = 0.0f;

    auto issue_tile = [&](int kt, int stage) {
        int k0 = kt * TBK;
        cp16(__cvta_generic_to_shared(&As[stage][ka][ma]),
             Ab + (size_t)(k0 + ka) * O_PAD + m0 + ma, (k0 + ka) < CC);
        cp16(__cvta_generic_to_shared(&Bs[stage][kb0][nb0]),
             Bb + (size_t)(k0 + kb0) * TT + n0 + nb0, (k0 + kb0) < CC);
        cp16(__cvta_generic_to_shared(&Bs[stage][kb1][nb1]),
             Bb + (size_t)(k0 + kb1) * TT + n0 + nb1, (k0 + kb1) < CC);
    };

    // Prologue: tile 0 -> stage 0
    issue_tile(0, 0);
    asm volatile("cp.async.commit_group;" ::: "memory");

    for (int kt = 0; kt < NTILES; kt++) {
        int stage = kt & 1;
        // Issue next tile (empty commit on last iteration keeps group count uniform)
        if (kt + 1 < NTILES) issue_tile(kt + 1, (kt + 1) & 1);
        asm volatile("cp.async.commit_group;" ::: "memory");
        // Wait until <=1 group outstanding -> tile kt resident
        asm volatile("cp.async.wait_group 1;" ::: "memory");
        __syncthreads();

#pragma unroll
        for (int kk = 0; kk < TBK; kk += 8) {
            uint32_t afrag[2][4];
#pragma unroll
            for (int mt = 0; mt < 2; mt++) {
                int mb = warpM * 32 + mt * 16;
                afrag[mt][0] = As[stage][kk + tig][mb + groupID];
                afrag[mt][1] = As[stage][kk + tig][mb + groupID + 8];
                afrag[mt][2] = As[stage][kk + tig + 4][mb + groupID];
                afrag[mt][3] = As[stage][kk + tig + 4][mb + groupID + 8];
            }
            uint32_t bfrag[4][2];
#pragma unroll
            for (int nt = 0; nt < 4; nt++) {
                int nb = warpN * 32 + nt * 8;
                bfrag[nt][0] = Bs[stage][kk + tig][nb + groupID];
                bfrag[nt][1] = Bs[stage][kk + tig + 4][nb + groupID];
            }
#pragma unroll
            for (int mt = 0; mt < 2; mt++)
#pragma unroll
                for (int nt = 0; nt < 4; nt++) {
                    asm volatile(
                        "mma.sync.aligned.m16n8k8.row.col.f32.tf32.tf32.f32 "
                        "{%0,%1,%2,%3}, {%4,%5,%6,%7}, {%8,%9}, {%0,%1,%2,%3};"
                        : "+f"(acc[mt][nt][0]), "+f"(acc[mt][nt][1]),
                          "+f"(acc[mt][nt][2]), "+f"(acc[mt][nt][3])
                        : "r"(afrag[mt][0]), "r"(afrag[mt][1]),
                          "r"(afrag[mt][2]), "r"(afrag[mt][3]),
                          "r"(bfrag[nt][0]), "r"(bfrag[nt][1]));
                }
        }
        __syncthreads();   // all warps done with this stage before it is refilled
    }

    // Epilogue
#pragma unroll
    for (int mt = 0; mt < 2; mt++) {
        int mrow0 = m0 + warpM * 32 + mt * 16 + groupID;
#pragma unroll
        for (int nt = 0; nt < 4; nt++) {
            int ncol = n0 + warpN * 32 + nt * 8 + tig * 2;
            if (mrow0 < OO) {
                float2 v = make_float2(acc[mt][nt][0], acc[mt][nt][1]);
                *(float2*)(Cb + (size_t)mrow0 * TT + ncol) = v;
            }
            if (mrow0 + 8 < OO) {
                float2 v = make_float2(acc[mt][nt][2], acc[mt][nt][3]);
                *(float2*)(Cb + (size_t)(mrow0 + 8) * TT + ncol) = v;
            }
        }
    }
}

// ---------------------------------------------------------------------------

extern "C" void kernel_launch(void* const* d_in, const int* in_sizes, int n_in,
                              void* d_out, int out_size) {
    const float* meg   = (const float*)d_in[0];   // [B,C,T]
    const float* pos   = (const float*)d_in[1];   // [B,C,2]
    const int*   subj  = (const int*)d_in[2];     // [B]
    const float* heads = (const float*)d_in[3];   // [200,O,D]
    float* out = (float*)d_out;                   // [B,O,T]

    float *p_embT, *p_hT, *p_w, *p_off;
    cudaGetSymbolAddress((void**)&p_embT, g_embT);
    cudaGetSymbolAddress((void**)&p_hT,   g_hT);
    cudaGetSymbolAddress((void**)&p_w,    g_w);
    cudaGetSymbolAddress((void**)&p_off,  g_off);

    // 1) Fourier embedding (transposed) + invalid offsets
    embed_kernel<<<dim3((CC + 31) / 32, BB), dim3(32, 8)>>>(pos);

    // 2) heads gather + transpose
    gather_heads_kernel<<<dim3((DD + 31) / 32, (OO + 31) / 32, BB), dim3(32, 8)>>>(heads, subj);

    // 3) scores[b][c][o] = sum_d embT[d][c] * hT[d][o] + off[c]  (fp32 exact)
    gemm_tn<64, 64, 16, 4, 4, true><<<dim3((OO + 63) / 64, (CC + 63) / 64, BB), 256>>>(
        p_embT, p_hT, p_w, p_off,
        CC, OO, DD,
        C_PAD, O_PAD, O_PAD,
        (size_t)DD * C_PAD, (size_t)DD * O_PAD, (size_t)CC * O_PAD);

    // 4) softmax over c per (b,o), in place, parallel over c slices
    softmax_kernel<<<dim3((OO + 31) / 32, BB), dim3(32, 8)>>>();

    // 5) out[b][o][t] = sum_c w[b][c][o] * meg[b][c][t]  -- TF32 + cp.async
    gemm_tf32_kernel<<<dim3(TT / TBN, (OO + TBM - 1) / TBM, BB), 256>>>(
        p_w, meg, out);
}

// round 9
// speedup vs baseline: 3.9974x; 1.3629x over previous
#include <cuda_runtime.h>
#include <math.h>
#include <stdint.h>

#define BB 32
#define CC 273
#define TT 4096
#define OO 270
#define DD 242
#define NF 11
#define C_PAD 288   // padded C stride for embT
#define O_PAD 272   // padded O stride for hT / weights

// Scratch (device globals: allocation-free). Extra pad covers tile-edge
// float4 / cp.async overreads.
__device__ __align__(16) float g_embT[(size_t)BB * DD * C_PAD + 1024]; // [b][d][c]
__device__ __align__(16) float g_hT  [(size_t)BB * DD * O_PAD + 1024]; // [b][d][o]
__device__ __align__(16) float g_w   [(size_t)BB * CC * O_PAD + 16384]; // [b][c][o]
__device__ float g_off[(size_t)BB * CC];

__device__ __forceinline__ uint32_t f2tf32(float f) {
    uint32_t r;
    asm("cvt.rna.tf32.f32 %0, %1;" : "=r"(r) : "f"(f));
    return r;
}

// ---------------------------------------------------------------------------
// Kernel 1: Fourier embedding, transposed [b][d][c], + invalid offset
// ---------------------------------------------------------------------------
__global__ void embed_kernel(const float* __restrict__ pos) {
    int b = blockIdx.y;
    int c = blockIdx.x * 32 + threadIdx.x;
    if (c >= CC) return;
    float x = pos[((size_t)b * CC + c) * 2 + 0];
    float y = pos[((size_t)b * CC + c) * 2 + 1];
    if (threadIdx.y == 0) {
        g_off[(size_t)b * CC + c] = (x == -0.1f && y == -0.1f) ? -1e9f : 0.0f;
    }
    const float scale = (float)(2.0 * 3.14159265358979323846 / 1.4);
    float px = x + 0.2f, py = y + 0.2f;
    float* eb = g_embT + (size_t)b * (DD * C_PAD);
    for (int k = threadIdx.y; k < NF * NF; k += blockDim.y) {
        int i = k / NF, j = k % NF;
        float loc = px * (scale * (float)i) + py * (scale * (float)j);
        float s, co;
        sincosf(loc, &s, &co);
        eb[(size_t)k * C_PAD + c] = co;
        eb[(size_t)(NF * NF + k) * C_PAD + c] = s;
    }
}

// ---------------------------------------------------------------------------
// Kernel 2: heads gather + transpose -> hT[b][d][o]
// ---------------------------------------------------------------------------
__global__ void gather_heads_kernel(const float* __restrict__ heads,
                                    const int* __restrict__ subj) {
    __shared__ float tile[32][33];
    int b = blockIdx.z;
    int s = subj[b];
    int d0 = blockIdx.x * 32;
    int o0 = blockIdx.y * 32;
    const float* hb = heads + (size_t)s * OO * DD;
    for (int oy = threadIdx.y; oy < 32; oy += blockDim.y) {
        int o = o0 + oy;
        int d = d0 + threadIdx.x;
        tile[oy][threadIdx.x] = (o < OO && d < DD) ? hb[(size_t)o * DD + d] : 0.0f;
    }
    __syncthreads();
    float* ht = g_hT + (size_t)b * (DD * O_PAD);
    for (int dy = threadIdx.y; dy < 32; dy += blockDim.y) {
        int d = d0 + dy;
        int o = o0 + threadIdx.x;
        if (d < DD && o < OO) ht[(size_t)d * O_PAD + o] = tile[threadIdx.x][dy];
    }
}

// ---------------------------------------------------------------------------
// fp32 SIMT GEMM (scores: keeps softmax inputs fp32-exact). C = A^T B.
// ---------------------------------------------------------------------------
template<int BM, int BN, int BK, int TM, int TN, bool OFF>
__global__ void gemm_tn(const float* __restrict__ A, const float* __restrict__ B,
                        float* __restrict__ C, const float* __restrict__ off,
                        int M, int N, int K,
                        int lda, int ldb, int ldc,
                        size_t sA, size_t sB, size_t sC) {
    constexpr int THREADS = (BM / TM) * (BN / TN);
    constexpr int NX = BN / TN;
    __shared__ float As[BK][BM];
    __shared__ float Bs[BK][BN];

    int b = blockIdx.z;
    const float* Ab = A + (size_t)b * sA;
    const float* Bb = B + (size_t)b * sB;
    float* Cb = C + (size_t)b * sC;

    int m0 = blockIdx.y * BM;
    int n0 = blockIdx.x * BN;
    int tid = threadIdx.x;
    int tx = tid % NX;
    int ty = tid / NX;

    float acc[TM][TN];
#pragma unroll
    for (int i = 0; i < TM; i++)
#pragma unroll
        for (int j = 0; j < TN; j++) acc[i][j] = 0.0f;

    for (int k0 = 0; k0 < K; k0 += BK) {
        for (int i = tid * 4; i < BK * BM; i += THREADS * 4) {
            int k = i / BM, m = i % BM;
            float4 v = make_float4(0.f, 0.f, 0.f, 0.f);
            if (k0 + k < K)
                v = *(const float4*)(Ab + (size_t)(k0 + k) * lda + m0 + m);
            *(float4*)(&As[k][m]) = v;
        }
        for (int i = tid * 4; i < BK * BN; i += THREADS * 4) {
            int k = i / BN, n = i % BN;
            float4 v = make_float4(0.f, 0.f, 0.f, 0.f);
            if (k0 + k < K)
                v = *(const float4*)(Bb + (size_t)(k0 + k) * ldb + n0 + n);
            *(float4*)(&Bs[k][n]) = v;
        }
        __syncthreads();
#pragma unroll
        for (int k = 0; k < BK; k++) {
            float a[TM], bb[TN];
#pragma unroll
            for (int i = 0; i < TM; i++) a[i] = As[k][ty * TM + i];
#pragma unroll
            for (int j = 0; j < TN; j++) bb[j] = Bs[k][tx * TN + j];
#pragma unroll
            for (int i = 0; i < TM; i++)
#pragma unroll
                for (int j = 0; j < TN; j++)
                    acc[i][j] = fmaf(a[i], bb[j], acc[i][j]);
        }
        __syncthreads();
    }

#pragma unroll
    for (int i = 0; i < TM; i++) {
        int m = m0 + ty * TM + i;
        if (m >= M) continue;
        float ofs = OFF ? off[(size_t)b * M + m] : 0.0f;
#pragma unroll
        for (int j = 0; j < TN; j++) {
            int n = n0 + tx * TN + j;
            if (n < N) Cb[(size_t)m * ldc + n] = acc[i][j] + ofs;
        }
    }
}

// ---------------------------------------------------------------------------
// Kernel 4: softmax over c per (b,o), in place. Block (32 o, 8 c-slices).
// Final weights are written PRE-ROUNDED to tf32 (cvt.rna) so the tensor-core
// GEMM's A operand needs no further conversion (raw bits pass through exact).
// ---------------------------------------------------------------------------
__global__ void softmax_kernel() {
    __shared__ float red[8][33];
    int b = blockIdx.y;
    int tx = threadIdx.x;          // o within tile
    int ty = threadIdx.y;          // c slice
    int o = blockIdx.x * 32 + tx;
    bool active = (o < OO);
    float* col = g_w + (size_t)b * (CC * O_PAD) + (active ? o : 0);

    float mx = -3.0e38f;
    for (int c = ty; c < CC; c += 8)
        if (active) mx = fmaxf(mx, col[(size_t)c * O_PAD]);
    red[ty][tx] = mx;
    __syncthreads();
    if (ty == 0) {
#pragma unroll
        for (int r = 1; r < 8; r++) mx = fmaxf(mx, red[r][tx]);
        red[0][tx] = mx;
    }
    __syncthreads();
    mx = red[0][tx];
    __syncthreads();

    float s = 0.0f;
    float e_loc[35];               // ceil(273/8)=35 slices max
    int ns = 0;
    for (int c = ty; c < CC; c += 8) {
        if (active) {
            float e = expf(col[(size_t)c * O_PAD] - mx);
            e_loc[ns] = e;
            s += e;
        }
        ns++;
    }
    red[ty][tx] = s;
    __syncthreads();
    if (ty == 0) {
#pragma unroll
        for (int r = 1; r < 8; r++) s += red[r][tx];
        red[0][tx] = 1.0f / s;
    }
    __syncthreads();
    float inv = red[0][tx];

    ns = 0;
    for (int c = ty; c < CC; c += 8) {
        if (active)
            col[(size_t)c * O_PAD] = __uint_as_float(f2tf32(e_loc[ns] * inv));
        ns++;
    }
}

// ---------------------------------------------------------------------------
// Kernel 5: TF32 tensor-core GEMM, 3-stage cp.async pipeline.
// out[b][m][n] = sum_k A[b][k][m] * B[b][k][n]
// A = g_w (pre-rounded tf32, lda=O_PAD), B = meg (ldb=TT). M=270,N=4096,K=273.
// 128 thr (4 warps along N), BM=64, BN=128, BK=16; warp tile 64x32 (4x4
// m16n8k8). Strides 72/136 (row step ≡ 8 mod 32 → conflict-free frag LDS).
// B fragments rounded to tf32 in registers (cvt.rna).
// ---------------------------------------------------------------------------
#define TBM 64
#define TBN 128
#define TBK 16
#define A_STR 72
#define B_STR 136
#define STAGES 3
#define NTILES ((CC + TBK - 1) / TBK)   // 18

__device__ __forceinline__ void cp16(uint32_t dst, const void* src, bool pred) {
    int sz = pred ? 16 : 0;
    asm volatile("cp.async.cg.shared.global [%0], [%1], 16, %2;"
                 :: "r"(dst), "l"(src), "r"(sz) : "memory");
}

__global__ __launch_bounds__(128) void gemm_tf32_kernel(
    const float* __restrict__ A, const float* __restrict__ B,
    float* __restrict__ C) {
    __shared__ uint32_t As[STAGES][TBK][A_STR];
    __shared__ uint32_t Bs[STAGES][TBK][B_STR];

    int b = blockIdx.z;
    const float* Ab = A + (size_t)b * ((size_t)CC * O_PAD);
    const float* Bb = B + (size_t)b * ((size_t)CC * TT);
    float* Cb = C + (size_t)b * ((size_t)OO * TT);

    int m0 = blockIdx.y * TBM;
    int n0 = blockIdx.x * TBN;
    int tid = threadIdx.x;
    int warpN = tid >> 5;          // 4 warps along N, warp tile 64x32
    int lane = tid & 31;
    int groupID = lane >> 2;
    int tig = lane & 3;

    // Per-thread fill coordinates (A: 2 chunks, B: 4 chunks of 16B)
    int ka[2], ma[2], kb[4], nb[4];
#pragma unroll
    for (int r = 0; r < 2; r++) {
        int ia = (tid + r * 128) * 4;
        ka[r] = ia / TBM; ma[r] = ia % TBM;
    }
#pragma unroll
    for (int r = 0; r < 4; r++) {
        int ib = (tid + r * 128) * 4;
        kb[r] = ib / TBN; nb[r] = ib % TBN;
    }

    float acc[4][4][4];
#pragma unroll
    for (int mt = 0; mt < 4; mt++)
#pragma unroll
        for (int nt = 0; nt < 4; nt++)
#pragma unroll
            for (int r = 0; r < 4; r++) acc[mt][nt][r] = 0.0f;

    auto issue_tile = [&](int kt, int stage) {
        int k0 = kt * TBK;
#pragma unroll
        for (int r = 0; r < 2; r++)
            cp16(__cvta_generic_to_shared(&As[stage][ka[r]][ma[r]]),
                 Ab + (size_t)(k0 + ka[r]) * O_PAD + m0 + ma[r], (k0 + ka[r]) < CC);
#pragma unroll
        for (int r = 0; r < 4; r++)
            cp16(__cvta_generic_to_shared(&Bs[stage][kb[r]][nb[r]]),
                 Bb + (size_t)(k0 + kb[r]) * TT + n0 + nb[r], (k0 + kb[r]) < CC);
    };

    // Prologue: tiles 0,1 -> stages 0,1
    issue_tile(0, 0);
    asm volatile("cp.async.commit_group;" ::: "memory");
    issue_tile(1, 1);
    asm volatile("cp.async.commit_group;" ::: "memory");

    for (int kt = 0; kt < NTILES; kt++) {
        int stage = kt % STAGES;
        if (kt + 2 < NTILES) issue_tile(kt + 2, (kt + 2) % STAGES);
        asm volatile("cp.async.commit_group;" ::: "memory");
        asm volatile("cp.async.wait_group 2;" ::: "memory");
        __syncthreads();

#pragma unroll
        for (int kk = 0; kk < TBK; kk += 8) {
            uint32_t afrag[4][4];
#pragma unroll
            for (int mt = 0; mt < 4; mt++) {
                int mb = mt * 16;
                afrag[mt][0] = As[stage][kk + tig][mb + groupID];
                afrag[mt][1] = As[stage][kk + tig][mb + groupID + 8];
                afrag[mt][2] = As[stage][kk + tig + 4][mb + groupID];
                afrag[mt][3] = As[stage][kk + tig + 4][mb + groupID + 8];
            }
            uint32_t bfrag[4][2];
#pragma unroll
            for (int nt = 0; nt < 4; nt++) {
                int nbase = warpN * 32 + nt * 8;
                bfrag[nt][0] = f2tf32(__uint_as_float(Bs[stage][kk + tig][nbase + groupID]));
                bfrag[nt][1] = f2tf32(__uint_as_float(Bs[stage][kk + tig + 4][nbase + groupID]));
            }
#pragma unroll
            for (int mt = 0; mt < 4; mt++)
#pragma unroll
                for (int nt = 0; nt < 4; nt++) {
                    asm volatile(
                        "mma.sync.aligned.m16n8k8.row.col.f32.tf32.tf32.f32 "
                        "{%0,%1,%2,%3}, {%4,%5,%6,%7}, {%8,%9}, {%0,%1,%2,%3};"
                        : "+f"(acc[mt][nt][0]), "+f"(acc[mt][nt][1]),
                          "+f"(acc[mt][nt][2]), "+f"(acc[mt][nt][3])
                        : "r"(afrag[mt][0]), "r"(afrag[mt][1]),
                          "r"(afrag[mt][2]), "r"(afrag[mt][3]),
                          "r"(bfrag[nt][0]), "r"(bfrag[nt][1]));
                }
        }
        __syncthreads();   // stage fully consumed before it is refilled
    }

    // Epilogue
#pragma unroll
    for (int mt = 0; mt < 4; mt++) {
        int mrow0 = m0 + mt * 16 + groupID;
#pragma unroll
        for (int nt = 0; nt < 4; nt++) {
            int ncol = n0 + warpN * 32 + nt * 8 + tig * 2;
            if (mrow0 < OO) {
                float2 v = make_float2(acc[mt][nt][0], acc[mt][nt][1]);
                *(float2*)(Cb + (size_t)mrow0 * TT + ncol) = v;
            }
            if (mrow0 + 8 < OO) {
                float2 v = make_float2(acc[mt][nt][2], acc[mt][nt][3]);
                *(float2*)(Cb + (size_t)(mrow0 + 8) * TT + ncol) = v;
            }
        }
    }
}

// ---------------------------------------------------------------------------

extern "C" void kernel_launch(void* const* d_in, const int* in_sizes, int n_in,
                              void* d_out, int out_size) {
    const float* meg   = (const float*)d_in[0];   // [B,C,T]
    const float* pos   = (const float*)d_in[1];   // [B,C,2]
    const int*   subj  = (const int*)d_in[2];     // [B]
    const float* heads = (const float*)d_in[3];   // [200,O,D]
    float* out = (float*)d_out;                   // [B,O,T]

    float *p_embT, *p_hT, *p_w, *p_off;
    cudaGetSymbolAddress((void**)&p_embT, g_embT);
    cudaGetSymbolAddress((void**)&p_hT,   g_hT);
    cudaGetSymbolAddress((void**)&p_w,    g_w);
    cudaGetSymbolAddress((void**)&p_off,  g_off);

    // 1) Fourier embedding (transposed) + invalid offsets
    embed_kernel<<<dim3((CC + 31) / 32, BB), dim3(32, 8)>>>(pos);

    // 2) heads gather + transpose
    gather_heads_kernel<<<dim3((DD + 31) / 32, (OO + 31) / 32, BB), dim3(32, 8)>>>(heads, subj);

    // 3) scores[b][c][o] = sum_d embT[d][c] * hT[d][o] + off[c]  (fp32 exact)
    gemm_tn<64, 64, 16, 4, 4, true><<<dim3((OO + 63) / 64, (CC + 63) / 64, BB), 256>>>(
        p_embT, p_hT, p_w, p_off,
        CC, OO, DD,
        C_PAD, O_PAD, O_PAD,
        (size_t)DD * C_PAD, (size_t)DD * O_PAD, (size_t)CC * O_PAD);

    // 4) softmax over c per (b,o), weights written tf32-rounded
    softmax_kernel<<<dim3((OO + 31) / 32, BB), dim3(32, 8)>>>();

    // 5) out[b][o][t] = sum_c w[b][c][o] * meg[b][c][t]  -- TF32 + cp.async x3
    gemm_tf32_kernel<<<dim3(TT / TBN, (OO + TBM - 1) / TBM, BB), 128>>>(
        p_w, meg, out);
}

// round 10
// speedup vs baseline: 4.9176x; 1.2302x over previous
#include <cuda_runtime.h>
#include <math.h>
#include <stdint.h>

#define BB 32
#define CC 273
#define TT 4096
#define OO 270
#define DD 242
#define NF 11
#define C_PAD 288   // padded C stride for embT
#define O_PAD 272   // padded O stride for hT / weights

// Scratch (device globals: allocation-free). Generous pads cover tile-edge
// cp.async address formation on the padded K/M/N ranges.
__device__ __align__(16) float g_embT[(size_t)BB * DD * C_PAD + 8192]; // [b][d][c]
__device__ __align__(16) float g_hT  [(size_t)BB * DD * O_PAD + 8192]; // [b][d][o]
__device__ __align__(16) float g_w   [(size_t)BB * CC * O_PAD + 16384]; // [b][c][o]
__device__ float g_off[(size_t)BB * CC];

__device__ __forceinline__ uint32_t f2tf32(float f) {
    uint32_t r;
    asm("cvt.rna.tf32.f32 %0, %1;" : "=r"(r) : "f"(f));
    return r;
}

__device__ __forceinline__ void cp16(uint32_t dst, const void* src, bool pred) {
    int sz = pred ? 16 : 0;
    asm volatile("cp.async.cg.shared.global [%0], [%1], 16, %2;"
                 :: "r"(dst), "l"(src), "r"(sz) : "memory");
}

#define MMA_TF32(acc, a0, a1, a2, a3, b0, b1)                                \
    asm volatile(                                                            \
        "mma.sync.aligned.m16n8k8.row.col.f32.tf32.tf32.f32 "                \
        "{%0,%1,%2,%3}, {%4,%5,%6,%7}, {%8,%9}, {%0,%1,%2,%3};"              \
        : "+f"((acc)[0]), "+f"((acc)[1]), "+f"((acc)[2]), "+f"((acc)[3])     \
        : "r"(a0), "r"(a1), "r"(a2), "r"(a3), "r"(b0), "r"(b1))

// ---------------------------------------------------------------------------
// Kernel 1: Fourier embedding, transposed [b][d][c], + invalid offset
// ---------------------------------------------------------------------------
__global__ void embed_kernel(const float* __restrict__ pos) {
    int b = blockIdx.y;
    int c = blockIdx.x * 32 + threadIdx.x;
    if (c >= CC) return;
    float x = pos[((size_t)b * CC + c) * 2 + 0];
    float y = pos[((size_t)b * CC + c) * 2 + 1];
    if (threadIdx.y == 0) {
        g_off[(size_t)b * CC + c] = (x == -0.1f && y == -0.1f) ? -1e9f : 0.0f;
    }
    const float scale = (float)(2.0 * 3.14159265358979323846 / 1.4);
    float px = x + 0.2f, py = y + 0.2f;
    float* eb = g_embT + (size_t)b * (DD * C_PAD);
    for (int k = threadIdx.y; k < NF * NF; k += blockDim.y) {
        int i = k / NF, j = k % NF;
        float loc = px * (scale * (float)i) + py * (scale * (float)j);
        float s, co;
        sincosf(loc, &s, &co);
        eb[(size_t)k * C_PAD + c] = co;
        eb[(size_t)(NF * NF + k) * C_PAD + c] = s;
    }
}

// ---------------------------------------------------------------------------
// Kernel 2: heads gather + transpose -> hT[b][d][o]
// ---------------------------------------------------------------------------
__global__ void gather_heads_kernel(const float* __restrict__ heads,
                                    const int* __restrict__ subj) {
    __shared__ float tile[32][33];
    int b = blockIdx.z;
    int s = subj[b];
    int d0 = blockIdx.x * 32;
    int o0 = blockIdx.y * 32;
    const float* hb = heads + (size_t)s * OO * DD;
    for (int oy = threadIdx.y; oy < 32; oy += blockDim.y) {
        int o = o0 + oy;
        int d = d0 + threadIdx.x;
        tile[oy][threadIdx.x] = (o < OO && d < DD) ? hb[(size_t)o * DD + d] : 0.0f;
    }
    __syncthreads();
    float* ht = g_hT + (size_t)b * (DD * O_PAD);
    for (int dy = threadIdx.y; dy < 32; dy += blockDim.y) {
        int d = d0 + dy;
        int o = o0 + threadIdx.x;
        if (d < DD && o < OO) ht[(size_t)d * O_PAD + o] = tile[threadIdx.x][dy];
    }
}

// ---------------------------------------------------------------------------
// Kernel 3: scores via 3xTF32 tensor cores (fp32-class accuracy).
// g_w[b][c][o] = sum_d embT[b][d][c] * hT[b][d][o] + off[b][c]
// M=273, N=270, K=242. BM=BN=64, BK=16; 128 thr, warps 2Mx2N, tile 32x32.
// Split: big=cvt.rna(x), small=cvt.rna(x-big); acc += Ab*Bb + Ab*Bs + As*Bb.
// ---------------------------------------------------------------------------
#define S_BM 64
#define S_BN 64
#define S_BK 16
#define S_STR 72        // 72 % 32 == 8 -> conflict-free fragment LDS
#define S_NT ((DD + S_BK - 1) / S_BK)   // 16

__global__ __launch_bounds__(128) void scores_kernel(
    const float* __restrict__ A, const float* __restrict__ B,
    float* __restrict__ C, const float* __restrict__ off) {
    __shared__ uint32_t As[3][S_BK][S_STR];
    __shared__ uint32_t Bs[3][S_BK][S_STR];

    int b = blockIdx.z;
    const float* Ab = A + (size_t)b * ((size_t)DD * C_PAD);
    const float* Bb = B + (size_t)b * ((size_t)DD * O_PAD);
    float* Cb = C + (size_t)b * ((size_t)CC * O_PAD);

    int m0 = blockIdx.y * S_BM;
    int n0 = blockIdx.x * S_BN;
    int tid = threadIdx.x;
    int warpId = tid >> 5;
    int lane = tid & 31;
    int warpM = warpId & 1;     // 2 warps along M
    int warpN = warpId >> 1;    // 2 warps along N
    int groupID = lane >> 2;
    int tig = lane & 3;

    int kq[2], mq[2];
#pragma unroll
    for (int r = 0; r < 2; r++) {
        int ia = (tid + r * 128) * 4;
        kq[r] = ia / S_BM; mq[r] = ia % S_BM;
    }

    float acc[2][4][4];
#pragma unroll
    for (int mt = 0; mt < 2; mt++)
#pragma unroll
        for (int nt = 0; nt < 4; nt++)
#pragma unroll
            for (int r = 0; r < 4; r++) acc[mt][nt][r] = 0.0f;

    auto issue = [&](int kt, int stage) {
        int k0 = kt * S_BK;
#pragma unroll
        for (int r = 0; r < 2; r++) {
            bool p = (k0 + kq[r]) < DD;
            cp16(__cvta_generic_to_shared(&As[stage][kq[r]][mq[r]]),
                 Ab + (size_t)(k0 + kq[r]) * C_PAD + m0 + mq[r], p);
            cp16(__cvta_generic_to_shared(&Bs[stage][kq[r]][mq[r]]),
                 Bb + (size_t)(k0 + kq[r]) * O_PAD + n0 + mq[r], p);
        }
    };

    issue(0, 0);
    asm volatile("cp.async.commit_group;" ::: "memory");
    issue(1, 1);
    asm volatile("cp.async.commit_group;" ::: "memory");

    for (int kt = 0; kt < S_NT; kt++) {
        int stage = kt % 3;
        if (kt + 2 < S_NT) issue(kt + 2, (kt + 2) % 3);
        asm volatile("cp.async.commit_group;" ::: "memory");
        asm volatile("cp.async.wait_group 2;" ::: "memory");
        __syncthreads();

#pragma unroll
        for (int kk = 0; kk < S_BK; kk += 8) {
            uint32_t aB[2][4], aS[2][4];
#pragma unroll
            for (int mt = 0; mt < 2; mt++) {
                int mb = warpM * 32 + mt * 16;
#pragma unroll
                for (int q = 0; q < 4; q++) {
                    int kr = kk + tig + (q >> 1) * 4;
                    int mc = mb + groupID + (q & 1) * 8;
                    float x = __uint_as_float(As[stage][kr][mc]);
                    uint32_t big = f2tf32(x);
                    aB[mt][q] = big;
                    aS[mt][q] = f2tf32(x - __uint_as_float(big));
                }
            }
            uint32_t bB[4][2], bS[4][2];
#pragma unroll
            for (int nt = 0; nt < 4; nt++) {
                int nb = warpN * 32 + nt * 8;
#pragma unroll
                for (int q = 0; q < 2; q++) {
                    float x = __uint_as_float(Bs[stage][kk + tig + q * 4][nb + groupID]);
                    uint32_t big = f2tf32(x);
                    bB[nt][q] = big;
                    bS[nt][q] = f2tf32(x - __uint_as_float(big));
                }
            }
#pragma unroll
            for (int mt = 0; mt < 2; mt++)
#pragma unroll
                for (int nt = 0; nt < 4; nt++) {
                    MMA_TF32(acc[mt][nt], aB[mt][0], aB[mt][1], aB[mt][2], aB[mt][3],
                             bS[nt][0], bS[nt][1]);
                    MMA_TF32(acc[mt][nt], aS[mt][0], aS[mt][1], aS[mt][2], aS[mt][3],
                             bB[nt][0], bB[nt][1]);
                    MMA_TF32(acc[mt][nt], aB[mt][0], aB[mt][1], aB[mt][2], aB[mt][3],
                             bB[nt][0], bB[nt][1]);
                }
        }
        __syncthreads();
    }

#pragma unroll
    for (int mt = 0; mt < 2; mt++) {
        int mrow0 = m0 + warpM * 32 + mt * 16 + groupID;
#pragma unroll
        for (int nt = 0; nt < 4; nt++) {
            int ncol = n0 + warpN * 32 + nt * 8 + tig * 2;
#pragma unroll
            for (int h = 0; h < 2; h++) {
                int m = mrow0 + h * 8;
                if (m < CC) {
                    float ofs = off[(size_t)b * CC + m];
                    if (ncol < OO)
                        Cb[(size_t)m * O_PAD + ncol] = acc[mt][nt][h * 2] + ofs;
                    if (ncol + 1 < OO)
                        Cb[(size_t)m * O_PAD + ncol + 1] = acc[mt][nt][h * 2 + 1] + ofs;
                }
            }
        }
    }
}

// ---------------------------------------------------------------------------
// Kernel 4: softmax over c per (b,o), in place. Block (32 o, 8 c-slices).
// Weights written PRE-ROUNDED to tf32 (A operand of big GEMM passes raw).
// ---------------------------------------------------------------------------
__global__ void softmax_kernel() {
    __shared__ float red[8][33];
    int b = blockIdx.y;
    int tx = threadIdx.x;
    int ty = threadIdx.y;
    int o = blockIdx.x * 32 + tx;
    bool active = (o < OO);
    float* col = g_w + (size_t)b * (CC * O_PAD) + (active ? o : 0);

    float mx = -3.0e38f;
    for (int c = ty; c < CC; c += 8)
        if (active) mx = fmaxf(mx, col[(size_t)c * O_PAD]);
    red[ty][tx] = mx;
    __syncthreads();
    if (ty == 0) {
#pragma unroll
        for (int r = 1; r < 8; r++) mx = fmaxf(mx, red[r][tx]);
        red[0][tx] = mx;
    }
    __syncthreads();
    mx = red[0][tx];
    __syncthreads();

    float s = 0.0f;
    float e_loc[35];
    int ns = 0;
    for (int c = ty; c < CC; c += 8) {
        if (active) {
            float e = expf(col[(size_t)c * O_PAD] - mx);
            e_loc[ns] = e;
            s += e;
        }
        ns++;
    }
    red[ty][tx] = s;
    __syncthreads();
    if (ty == 0) {
#pragma unroll
        for (int r = 1; r < 8; r++) s += red[r][tx];
        red[0][tx] = 1.0f / s;
    }
    __syncthreads();
    float inv = red[0][tx];

    ns = 0;
    for (int c = ty; c < CC; c += 8) {
        if (active)
            col[(size_t)c * O_PAD] = __uint_as_float(f2tf32(e_loc[ns] * inv));
        ns++;
    }
}

// ---------------------------------------------------------------------------
// Kernel 5: TF32 tensor-core GEMM, 3-stage cp.async pipeline.
// out[b][m][n] = sum_k w[b][k][m] * meg[b][k][n]; M=270,N=4096,K=273.
// BM=96 (3 M-tiles: cuts B L2 re-reads + M waste), BN=128, BK=16.
// 128 thr, 4 warps along N; warp tile 96x32 (6x4 m16n8k8).
// Strides 104/136 (≡8 mod 32): conflict-free fragment LDS.
// A pre-rounded tf32 (softmax); B cvt.rna in registers.
// ---------------------------------------------------------------------------
#define TBM 96
#define TBN 128
#define TBK 16
#define A_STR 104
#define B_STR 136
#define NTILES ((CC + TBK - 1) / TBK)   // 18

__global__ __launch_bounds__(128, 3) void gemm_tf32_kernel(
    const float* __restrict__ A, const float* __restrict__ B,
    float* __restrict__ C) {
    __shared__ uint32_t As[3][TBK][A_STR];
    __shared__ uint32_t Bs[3][TBK][B_STR];

    int b = blockIdx.z;
    const float* Ab = A + (size_t)b * ((size_t)CC * O_PAD);
    const float* Bb = B + (size_t)b * ((size_t)CC * TT);
    float* Cb = C + (size_t)b * ((size_t)OO * TT);

    int m0 = blockIdx.y * TBM;
    int n0 = blockIdx.x * TBN;
    int tid = threadIdx.x;
    int warpN = tid >> 5;
    int lane = tid & 31;
    int groupID = lane >> 2;
    int tig = lane & 3;

    int ka[3], ma[3], kb[4], nb[4];
#pragma unroll
    for (int r = 0; r < 3; r++) {
        int ia = (tid + r * 128) * 4;
        ka[r] = ia / TBM; ma[r] = ia % TBM;
    }
#pragma unroll
    for (int r = 0; r < 4; r++) {
        int ib = (tid + r * 128) * 4;
        kb[r] = ib / TBN; nb[r] = ib % TBN;
    }

    float acc[6][4][4];
#pragma unroll
    for (int mt = 0; mt < 6; mt++)
#pragma unroll
        for (int nt = 0; nt < 4; nt++)
#pragma unroll
            for (int r = 0; r < 4; r++) acc[mt][nt][r] = 0.0f;

    auto issue_tile = [&](int kt, int stage) {
        int k0 = kt * TBK;
#pragma unroll
        for (int r = 0; r < 3; r++)
            cp16(__cvta_generic_to_shared(&As[stage][ka[r]][ma[r]]),
                 Ab + (size_t)(k0 + ka[r]) * O_PAD + m0 + ma[r], (k0 + ka[r]) < CC);
#pragma unroll
        for (int r = 0; r < 4; r++)
            cp16(__cvta_generic_to_shared(&Bs[stage][kb[r]][nb[r]]),
                 Bb + (size_t)(k0 + kb[r]) * TT + n0 + nb[r], (k0 + kb[r]) < CC);
    };

    issue_tile(0, 0);
    asm volatile("cp.async.commit_group;" ::: "memory");
    issue_tile(1, 1);
    asm volatile("cp.async.commit_group;" ::: "memory");

    for (int kt = 0; kt < NTILES; kt++) {
        int stage = kt % 3;
        if (kt + 2 < NTILES) issue_tile(kt + 2, (kt + 2) % 3);
        asm volatile("cp.async.commit_group;" ::: "memory");
        asm volatile("cp.async.wait_group 2;" ::: "memory");
        __syncthreads();

#pragma unroll
        for (int kk = 0; kk < TBK; kk += 8) {
            uint32_t afrag[6][4];
#pragma unroll
            for (int mt = 0; mt < 6; mt++) {
                int mb = mt * 16;
                afrag[mt][0] = As[stage][kk + tig][mb + groupID];
                afrag[mt][1] = As[stage][kk + tig][mb + groupID + 8];
                afrag[mt][2] = As[stage][kk + tig + 4][mb + groupID];
                afrag[mt][3] = As[stage][kk + tig + 4][mb + groupID + 8];
            }
            uint32_t bfrag[4][2];
#pragma unroll
            for (int nt = 0; nt < 4; nt++) {
                int nbase = warpN * 32 + nt * 8;
                bfrag[nt][0] = f2tf32(__uint_as_float(Bs[stage][kk + tig][nbase + groupID]));
                bfrag[nt][1] = f2tf32(__uint_as_float(Bs[stage][kk + tig + 4][nbase + groupID]));
            }
#pragma unroll
            for (int mt = 0; mt < 6; mt++)
#pragma unroll
                for (int nt = 0; nt < 4; nt++)
                    MMA_TF32(acc[mt][nt], afrag[mt][0], afrag[mt][1],
                             afrag[mt][2], afrag[mt][3],
                             bfrag[nt][0], bfrag[nt][1]);
        }
        __syncthreads();
    }

#pragma unroll
    for (int mt = 0; mt < 6; mt++) {
        int mrow0 = m0 + mt * 16 + groupID;
#pragma unroll
        for (int nt = 0; nt < 4; nt++) {
            int ncol = n0 + warpN * 32 + nt * 8 + tig * 2;
            if (mrow0 < OO) {
                float2 v = make_float2(acc[mt][nt][0], acc[mt][nt][1]);
                *(float2*)(Cb + (size_t)mrow0 * TT + ncol) = v;
            }
            if (mrow0 + 8 < OO) {
                float2 v = make_float2(acc[mt][nt][2], acc[mt][nt][3]);
                *(float2*)(Cb + (size_t)(mrow0 + 8) * TT + ncol) = v;
            }
        }
    }
}

// ---------------------------------------------------------------------------

extern "C" void kernel_launch(void* const* d_in, const int* in_sizes, int n_in,
                              void* d_out, int out_size) {
    const float* meg   = (const float*)d_in[0];   // [B,C,T]
    const float* pos   = (const float*)d_in[1];   // [B,C,2]
    const int*   subj  = (const int*)d_in[2];     // [B]
    const float* heads = (const float*)d_in[3];   // [200,O,D]
    float* out = (float*)d_out;                   // [B,O,T]

    float *p_embT, *p_hT, *p_w, *p_off;
    cudaGetSymbolAddress((void**)&p_embT, g_embT);
    cudaGetSymbolAddress((void**)&p_hT,   g_hT);
    cudaGetSymbolAddress((void**)&p_w,    g_w);
    cudaGetSymbolAddress((void**)&p_off,  g_off);

    // 1) Fourier embedding (transposed) + invalid offsets
    embed_kernel<<<dim3((CC + 31) / 32, BB), dim3(32, 8)>>>(pos);

    // 2) heads gather + transpose
    gather_heads_kernel<<<dim3((DD + 31) / 32, (OO + 31) / 32, BB), dim3(32, 8)>>>(heads, subj);

    // 3) scores via 3xTF32 tensor cores
    scores_kernel<<<dim3((OO + S_BN - 1) / S_BN, (CC + S_BM - 1) / S_BM, BB), 128>>>(
        p_embT, p_hT, p_w, p_off);

    // 4) softmax over c per (b,o), weights written tf32-rounded
    softmax_kernel<<<dim3((OO + 31) / 32, BB), dim3(32, 8)>>>();

    // 5) out[b][o][t] = sum_c w[b][c][o] * meg[b][c][t]  -- TF32, BM=96
    gemm_tf32_kernel<<<dim3(TT / TBN, (OO + TBM - 1) / TBM, BB), 128>>>(
        p_w, meg, out);
}